// round 2
// baseline (speedup 1.0000x reference)
#include <cuda_runtime.h>
#include <cuda_bf16.h>
#include <cstdint>

// ---------------------------------------------------------------------------
// EigenGIN: 3x GINConv(sum-agg + Linear + ReLU, residual) + final projection.
// x:[N,64] f32, edge_index:[2,E] int32 (JAX x64 disabled -> int32 on device),
// W0:[64,128], W1,W2:[128,128], Wp:[128,32], out:[N,32] f32
// ---------------------------------------------------------------------------

#define MAX_NODES 50000

// Scratch (device globals: no allocation allowed)
__device__ float g_agg[MAX_NODES * 128];
__device__ float g_h0 [MAX_NODES * 128];
__device__ float g_h1 [MAX_NODES * 128];

// ---------------------------------------------------------------------------
// Aggregation: one warp per edge. Gather feat[src] (vectorized), atomicAdd
// into agg[dst]. Feature tables are L2-resident (<=25.6MB).
// ---------------------------------------------------------------------------
template <int DIM>
__global__ void agg_kernel(const float* __restrict__ feat,
                           const int* __restrict__ ei,
                           float* __restrict__ agg,
                           int n_edges)
{
    int gw   = (blockIdx.x * blockDim.x + threadIdx.x) >> 5;
    int lane = threadIdx.x & 31;
    if (gw >= n_edges) return;

    int s = __ldg(&ei[gw]);
    int d = __ldg(&ei[n_edges + gw]);

    if (DIM == 128) {
        const float4* sp = reinterpret_cast<const float4*>(feat + (size_t)s * 128);
        float4 v = __ldg(&sp[lane]);
        float* dp = agg + (size_t)d * 128 + lane * 4;
        atomicAdd(dp + 0, v.x);
        atomicAdd(dp + 1, v.y);
        atomicAdd(dp + 2, v.z);
        atomicAdd(dp + 3, v.w);
    } else { // DIM == 64
        const float2* sp = reinterpret_cast<const float2*>(feat + (size_t)s * 64);
        float2 v = __ldg(&sp[lane]);
        float* dp = agg + (size_t)d * 64 + lane * 2;
        atomicAdd(dp + 0, v.x);
        atomicAdd(dp + 1, v.y);
    }
}

// ---------------------------------------------------------------------------
// Fused GEMM: OUT = [relu]((X [+ AGG]) @ W + b) [+ RES]
// BM=64 rows/block, BK=32 k-chunk, register micro-tile TM x TN, 256 threads.
// ---------------------------------------------------------------------------
template <int K, int N, int TM, int TN, bool HAS_AGG, bool RELU, bool RESID>
__global__ __launch_bounds__(256)
void gemm_kernel(const float* __restrict__ X,
                 const float* __restrict__ AGG,
                 const float* __restrict__ W,
                 const float* __restrict__ Bv,
                 const float* __restrict__ RES,
                 float* __restrict__ OUT,
                 int nrows)
{
    constexpr int BM = 64;
    constexpr int BK = 32;
    constexpr int NC = N / TN;   // threads along columns
    constexpr int NR = BM / TM;  // threads along rows
    static_assert(NC * NR == 256, "thread tiling must be 256");

    __shared__ float sA[BK][BM + 1]; // transposed: sA[kk][row], padded
    __shared__ float sW[BK][N];

    const int t    = threadIdx.x;
    const int ct   = t % NC;
    const int rt   = t / NC;
    const int row0 = blockIdx.x * BM;

    float acc[TM][TN];
#pragma unroll
    for (int v = 0; v < TM; v++)
#pragma unroll
        for (int u = 0; u < TN; u++) acc[v][u] = 0.0f;

    for (int k0 = 0; k0 < K; k0 += BK) {
        // Load A chunk (BM x BK), transposed into smem. Coalesced on k.
#pragma unroll
        for (int it = 0; it < (BM * BK) / 256; it++) {
            int i  = t + it * 256;
            int kk = i % BK;
            int r  = i / BK;
            int row = row0 + r;
            float v = 0.0f;
            if (row < nrows) {
                size_t off = (size_t)row * K + k0 + kk;
                v = X[off];
                if (HAS_AGG) v += AGG[off];
            }
            sA[kk][r] = v;
        }
        // Load W chunk (BK x N). Coalesced on j.
#pragma unroll
        for (int it = 0; it < (BK * N) / 256; it++) {
            int i  = t + it * 256;
            int j  = i % N;
            int kk = i / N;
            sW[kk][j] = W[(size_t)(k0 + kk) * N + j];
        }
        __syncthreads();

#pragma unroll
        for (int kk = 0; kk < BK; kk++) {
            float a[TM], b[TN];
#pragma unroll
            for (int v = 0; v < TM; v++) a[v] = sA[kk][rt + NR * v];
#pragma unroll
            for (int u = 0; u < TN; u++) b[u] = sW[kk][ct + NC * u];
#pragma unroll
            for (int v = 0; v < TM; v++)
#pragma unroll
                for (int u = 0; u < TN; u++)
                    acc[v][u] = fmaf(a[v], b[u], acc[v][u]);
        }
        __syncthreads();
    }

    // Epilogue
#pragma unroll
    for (int v = 0; v < TM; v++) {
        int row = row0 + rt + NR * v;
        if (row >= nrows) continue;
#pragma unroll
        for (int u = 0; u < TN; u++) {
            int j = ct + NC * u;
            float o = acc[v][u] + __ldg(&Bv[j]);
            if (RELU) o = fmaxf(o, 0.0f);
            if (RESID) o += RES[(size_t)row * N + j];
            OUT[(size_t)row * N + j] = o;
        }
    }
}

// ---------------------------------------------------------------------------
// Launch
// ---------------------------------------------------------------------------
extern "C" void kernel_launch(void* const* d_in, const int* in_sizes, int n_in,
                              void* d_out, int out_size)
{
    const float* x  = (const float*)d_in[0];
    const int*   ei = (const int*)d_in[1];
    const float* W0 = (const float*)d_in[2];
    const float* b0 = (const float*)d_in[3];
    const float* W1 = (const float*)d_in[4];
    const float* b1 = (const float*)d_in[5];
    const float* W2 = (const float*)d_in[6];
    const float* b2 = (const float*)d_in[7];
    const float* Wp = (const float*)d_in[8];
    const float* bp = (const float*)d_in[9];
    float* out = (float*)d_out;

    const int n_nodes = in_sizes[0] / 64;
    const int n_edges = in_sizes[1] / 2;

    float *agg, *h0, *h1;
    cudaGetSymbolAddress((void**)&agg, g_agg);
    cudaGetSymbolAddress((void**)&h0,  g_h0);
    cudaGetSymbolAddress((void**)&h1,  g_h1);
    float* h2 = h0; // reuse after layer 2 (h0 dead once layer-2 inputs are h1)

    const int AGG_THREADS = 256;                      // 8 warps/block
    const int agg_blocks  = (n_edges + 7) / 8;        // one warp per edge
    const int gemm_blocks = (n_nodes + 63) / 64;

    // ---- Layer 0: h0 = relu((x + sum_agg(x)) @ W0 + b0)
    cudaMemsetAsync(agg, 0, (size_t)n_nodes * 64 * sizeof(float));
    agg_kernel<64><<<agg_blocks, AGG_THREADS>>>(x, ei, agg, n_edges);
    gemm_kernel<64, 128, 8, 4, true, true, false>
        <<<gemm_blocks, 256>>>(x, agg, W0, b0, nullptr, h0, n_nodes);

    // ---- Layer 1: h1 = relu((h0 + sum_agg(h0)) @ W1 + b1) + h0
    cudaMemsetAsync(agg, 0, (size_t)n_nodes * 128 * sizeof(float));
    agg_kernel<128><<<agg_blocks, AGG_THREADS>>>(h0, ei, agg, n_edges);
    gemm_kernel<128, 128, 8, 4, true, true, true>
        <<<gemm_blocks, 256>>>(h0, agg, W1, b1, h0, h1, n_nodes);

    // ---- Layer 2: h2 = relu((h1 + sum_agg(h1)) @ W2 + b2) + h1
    cudaMemsetAsync(agg, 0, (size_t)n_nodes * 128 * sizeof(float));
    agg_kernel<128><<<agg_blocks, AGG_THREADS>>>(h1, ei, agg, n_edges);
    gemm_kernel<128, 128, 8, 4, true, true, true>
        <<<gemm_blocks, 256>>>(h1, agg, W2, b2, h1, h2, n_nodes);

    // ---- Projection: out = h2 @ Wp + bp
    gemm_kernel<128, 32, 2, 4, false, false, false>
        <<<gemm_blocks, 256>>>(h2, nullptr, Wp, bp, nullptr, out, n_nodes);
}

// round 3
// speedup vs baseline: 1.7183x; 1.7183x over previous
#include <cuda_runtime.h>
#include <cuda_bf16.h>
#include <cstdint>

// ---------------------------------------------------------------------------
// EigenGIN: 3x GINConv(sum-agg + Linear + ReLU, residual) + final projection.
// x:[N,64] f32, edge_index:[2,E] int32, W0:[64,128], W1,W2:[128,128],
// Wp:[128,32], out:[N,32] f32
// ---------------------------------------------------------------------------

#define MAX_NODES 50000

// Scratch (device globals: no allocation allowed)
__device__ float g_agg[MAX_NODES * 128];
__device__ float g_h0 [MAX_NODES * 128];
__device__ float g_h1 [MAX_NODES * 128];

// Vector reduction to global: one L2 op per 16B (sm_90+)
__device__ __forceinline__ void red_add_v4(float* addr, float4 v) {
    asm volatile("red.global.add.v4.f32 [%0], {%1, %2, %3, %4};"
                 :: "l"(addr), "f"(v.x), "f"(v.y), "f"(v.z), "f"(v.w)
                 : "memory");
}

// ---------------------------------------------------------------------------
// Aggregation (DIM=128): one warp per edge; 32 lanes x float4 gather + red.v4.
// ---------------------------------------------------------------------------
__global__ void agg128_kernel(const float* __restrict__ feat,
                              const int* __restrict__ ei,
                              float* __restrict__ agg,
                              int n_edges)
{
    int gw   = (blockIdx.x * blockDim.x + threadIdx.x) >> 5;
    int lane = threadIdx.x & 31;
    if (gw >= n_edges) return;

    int s = __ldg(&ei[gw]);
    int d = __ldg(&ei[n_edges + gw]);

    const float4* sp = reinterpret_cast<const float4*>(feat + (size_t)s * 128);
    float4 v = __ldg(&sp[lane]);
    red_add_v4(agg + (size_t)d * 128 + lane * 4, v);
}

// ---------------------------------------------------------------------------
// Aggregation (DIM=64): one warp handles TWO edges; 16 lanes x float4 each.
// ---------------------------------------------------------------------------
__global__ void agg64_kernel(const float* __restrict__ feat,
                             const int* __restrict__ ei,
                             float* __restrict__ agg,
                             int n_edges)
{
    int gw   = (blockIdx.x * blockDim.x + threadIdx.x) >> 5;
    int lane = threadIdx.x & 31;
    int e    = gw * 2 + (lane >> 4);   // edge index for this half-warp
    int sub  = lane & 15;
    if (e >= n_edges) return;

    int s = __ldg(&ei[e]);
    int d = __ldg(&ei[n_edges + e]);

    const float4* sp = reinterpret_cast<const float4*>(feat + (size_t)s * 64);
    float4 v = __ldg(&sp[sub]);
    red_add_v4(agg + (size_t)d * 64 + sub * 4, v);
}

// ---------------------------------------------------------------------------
// Fused GEMM: OUT = [relu]((X [+ AGG]) @ W + b) [+ RES]
// BM=64 rows/block, BK=32 k-chunk, register micro-tile TM x TN, 256 threads.
// ---------------------------------------------------------------------------
template <int K, int N, int TM, int TN, bool HAS_AGG, bool RELU, bool RESID>
__global__ __launch_bounds__(256)
void gemm_kernel(const float* __restrict__ X,
                 const float* __restrict__ AGG,
                 const float* __restrict__ W,
                 const float* __restrict__ Bv,
                 const float* __restrict__ RES,
                 float* __restrict__ OUT,
                 int nrows)
{
    constexpr int BM = 64;
    constexpr int BK = 32;
    constexpr int NC = N / TN;   // threads along columns
    constexpr int NR = BM / TM;  // threads along rows
    static_assert(NC * NR == 256, "thread tiling must be 256");

    __shared__ float sA[BK][BM + 1]; // transposed: sA[kk][row], padded
    __shared__ float sW[BK][N];

    const int t    = threadIdx.x;
    const int ct   = t % NC;
    const int rt   = t / NC;
    const int row0 = blockIdx.x * BM;

    float acc[TM][TN];
#pragma unroll
    for (int v = 0; v < TM; v++)
#pragma unroll
        for (int u = 0; u < TN; u++) acc[v][u] = 0.0f;

    for (int k0 = 0; k0 < K; k0 += BK) {
        // Load A chunk (BM x BK), transposed into smem. Coalesced on k.
#pragma unroll
        for (int it = 0; it < (BM * BK) / 256; it++) {
            int i  = t + it * 256;
            int kk = i % BK;
            int r  = i / BK;
            int row = row0 + r;
            float v = 0.0f;
            if (row < nrows) {
                size_t off = (size_t)row * K + k0 + kk;
                v = X[off];
                if (HAS_AGG) v += AGG[off];
            }
            sA[kk][r] = v;
        }
        // Load W chunk (BK x N). Coalesced on j.
#pragma unroll
        for (int it = 0; it < (BK * N) / 256; it++) {
            int i  = t + it * 256;
            int j  = i % N;
            int kk = i / N;
            sW[kk][j] = W[(size_t)(k0 + kk) * N + j];
        }
        __syncthreads();

#pragma unroll
        for (int kk = 0; kk < BK; kk++) {
            float a[TM], b[TN];
#pragma unroll
            for (int v = 0; v < TM; v++) a[v] = sA[kk][rt + NR * v];
#pragma unroll
            for (int u = 0; u < TN; u++) b[u] = sW[kk][ct + NC * u];
#pragma unroll
            for (int v = 0; v < TM; v++)
#pragma unroll
                for (int u = 0; u < TN; u++)
                    acc[v][u] = fmaf(a[v], b[u], acc[v][u]);
        }
        __syncthreads();
    }

    // Epilogue
#pragma unroll
    for (int v = 0; v < TM; v++) {
        int row = row0 + rt + NR * v;
        if (row >= nrows) continue;
#pragma unroll
        for (int u = 0; u < TN; u++) {
            int j = ct + NC * u;
            float o = acc[v][u] + __ldg(&Bv[j]);
            if (RELU) o = fmaxf(o, 0.0f);
            if (RESID) o += RES[(size_t)row * N + j];
            OUT[(size_t)row * N + j] = o;
        }
    }
}

// ---------------------------------------------------------------------------
// Launch
// ---------------------------------------------------------------------------
extern "C" void kernel_launch(void* const* d_in, const int* in_sizes, int n_in,
                              void* d_out, int out_size)
{
    const float* x  = (const float*)d_in[0];
    const int*   ei = (const int*)d_in[1];
    const float* W0 = (const float*)d_in[2];
    const float* b0 = (const float*)d_in[3];
    const float* W1 = (const float*)d_in[4];
    const float* b1 = (const float*)d_in[5];
    const float* W2 = (const float*)d_in[6];
    const float* b2 = (const float*)d_in[7];
    const float* Wp = (const float*)d_in[8];
    const float* bp = (const float*)d_in[9];
    float* out = (float*)d_out;

    const int n_nodes = in_sizes[0] / 64;
    const int n_edges = in_sizes[1] / 2;

    float *agg, *h0, *h1;
    cudaGetSymbolAddress((void**)&agg, g_agg);
    cudaGetSymbolAddress((void**)&h0,  g_h0);
    cudaGetSymbolAddress((void**)&h1,  g_h1);
    float* h2 = h0; // reuse after layer 2 (h0 dead once layer-2 inputs are h1)

    const int AGG_THREADS  = 256;                       // 8 warps/block
    const int agg_blocks   = (n_edges + 7) / 8;         // warp per edge (dim128)
    const int agg64_blocks = (n_edges + 15) / 16;       // warp per 2 edges (dim64)
    const int gemm_blocks  = (n_nodes + 63) / 64;

    // ---- Layer 0: h0 = relu((x + sum_agg(x)) @ W0 + b0)
    cudaMemsetAsync(agg, 0, (size_t)n_nodes * 64 * sizeof(float));
    agg64_kernel<<<agg64_blocks, AGG_THREADS>>>(x, ei, agg, n_edges);
    gemm_kernel<64, 128, 8, 4, true, true, false>
        <<<gemm_blocks, 256>>>(x, agg, W0, b0, nullptr, h0, n_nodes);

    // ---- Layer 1: h1 = relu((h0 + sum_agg(h0)) @ W1 + b1) + h0
    cudaMemsetAsync(agg, 0, (size_t)n_nodes * 128 * sizeof(float));
    agg128_kernel<<<agg_blocks, AGG_THREADS>>>(h0, ei, agg, n_edges);
    gemm_kernel<128, 128, 8, 4, true, true, true>
        <<<gemm_blocks, 256>>>(h0, agg, W1, b1, h0, h1, n_nodes);

    // ---- Layer 2: h2 = relu((h1 + sum_agg(h1)) @ W2 + b2) + h1
    cudaMemsetAsync(agg, 0, (size_t)n_nodes * 128 * sizeof(float));
    agg128_kernel<<<agg_blocks, AGG_THREADS>>>(h1, ei, agg, n_edges);
    gemm_kernel<128, 128, 8, 4, true, true, true>
        <<<gemm_blocks, 256>>>(h1, agg, W2, b2, h1, h2, n_nodes);

    // ---- Projection: out = h2 @ Wp + bp
    gemm_kernel<128, 32, 2, 4, false, false, false>
        <<<gemm_blocks, 256>>>(h2, nullptr, Wp, bp, nullptr, out, n_nodes);
}

// round 5
// speedup vs baseline: 1.8293x; 1.0646x over previous
#include <cuda_runtime.h>
#include <cuda_bf16.h>
#include <cstdint>

// ---------------------------------------------------------------------------
// EigenGIN: 3x GINConv(sum-agg + Linear + ReLU, residual) + projection.
// GEMMs via ldmatrix + mma.sync bf16 (pair-split for fp32-grade accuracy).
// Aggregation via red.global.add.v4.f32 (one L2 op per 16B).
// ---------------------------------------------------------------------------

#define MAX_NODES 50000

__device__ float g_agg[MAX_NODES * 128];
__device__ float g_h0 [MAX_NODES * 128];
__device__ float g_h1 [MAX_NODES * 128];

// ===================== helpers ====================
__device__ __forceinline__ uint32_t smem_u32(const void* p) {
    uint32_t a;
    asm("{ .reg .u64 t; cvta.to.shared.u64 t, %1; cvt.u32.u64 %0, t; }"
        : "=r"(a) : "l"(p));
    return a;
}

#define LDMATRIX_X4(R0, R1, R2, R3, ADDR) \
    asm volatile("ldmatrix.sync.aligned.m8n8.x4.shared.b16 {%0,%1,%2,%3}, [%4];" \
                 : "=r"(R0), "=r"(R1), "=r"(R2), "=r"(R3) : "r"(ADDR))

__device__ __forceinline__ void mma_bf16(float* c, const uint32_t* a, const uint32_t* b) {
    asm volatile(
        "mma.sync.aligned.m16n8k16.row.col.f32.bf16.bf16.f32 "
        "{%0,%1,%2,%3}, {%4,%5,%6,%7}, {%8,%9}, {%0,%1,%2,%3};"
        : "+f"(c[0]), "+f"(c[1]), "+f"(c[2]), "+f"(c[3])
        : "r"(a[0]), "r"(a[1]), "r"(a[2]), "r"(a[3]), "r"(b[0]), "r"(b[1]));
}

__device__ __forceinline__ uint32_t pack_bf2(__nv_bfloat16 a, __nv_bfloat16 b) {
    return (uint32_t)__bfloat16_as_ushort(a) | ((uint32_t)__bfloat16_as_ushort(b) << 16);
}
__device__ __forceinline__ void split2(float f, __nv_bfloat16& h, __nv_bfloat16& l) {
    h = __float2bfloat16(f);
    l = __float2bfloat16(f - __bfloat162float(h));
}

// ===================== Aggregation ====================
__device__ __forceinline__ void red_add_v4(float* addr, float4 v) {
    asm volatile("red.global.add.v4.f32 [%0], {%1, %2, %3, %4};"
                 :: "l"(addr), "f"(v.x), "f"(v.y), "f"(v.z), "f"(v.w) : "memory");
}

__global__ void agg128_kernel(const float* __restrict__ feat,
                              const int* __restrict__ ei,
                              float* __restrict__ agg, int n_edges)
{
    int gw = (blockIdx.x * blockDim.x + threadIdx.x) >> 5;
    int lane = threadIdx.x & 31;
    if (gw >= n_edges) return;
    int s = __ldg(&ei[gw]);
    int d = __ldg(&ei[n_edges + gw]);
    const float4* sp = reinterpret_cast<const float4*>(feat + (size_t)s * 128);
    float4 v = __ldg(&sp[lane]);
    red_add_v4(agg + (size_t)d * 128 + lane * 4, v);
}

__global__ void agg64_kernel(const float* __restrict__ feat,
                             const int* __restrict__ ei,
                             float* __restrict__ agg, int n_edges)
{
    int gw = (blockIdx.x * blockDim.x + threadIdx.x) >> 5;
    int lane = threadIdx.x & 31;
    int e = gw * 2 + (lane >> 4);
    int sub = lane & 15;
    if (e >= n_edges) return;
    int s = __ldg(&ei[e]);
    int d = __ldg(&ei[n_edges + e]);
    const float4* sp = reinterpret_cast<const float4*>(feat + (size_t)s * 64);
    float4 v = __ldg(&sp[sub]);
    red_add_v4(agg + (size_t)d * 64 + sub * 4, v);
}

// ===================== mma.sync GEMM ====================
// OUT[M,N] = [relu]((X [+AGG]) @ W + b) [+RES];  W is [K,N] row-major.
// A: [128][K] bf16 hi/lo (padded stride), B = W^T: [N][K] bf16 hi/lo.
// Warps: 4 along M (32 rows each) x 2 along N (N/2 cols each).
template <int K, int N, bool HAS_AGG, bool RELU, bool RESID>
__global__ __launch_bounds__(256)
void gemm_mma(const float* __restrict__ X,
              const float* __restrict__ AGG,
              const float* __restrict__ W,
              const float* __restrict__ Bv,
              const float* __restrict__ RES,
              float* __restrict__ OUT,
              int nrows)
{
    constexpr int BM = 128;
    constexpr int SK = K + 8;       // bf16 elements per row (padded)
    constexpr int WN = N / 2;       // cols per warp-column
    constexpr int NT = WN / 8;      // n8 tiles per warp
    constexpr int KS = K / 16;      // k16 steps

    extern __shared__ __nv_bfloat16 smem[];
    __nv_bfloat16* Ah = smem;
    __nv_bfloat16* Al = Ah + BM * SK;
    __nv_bfloat16* Bh = Al + BM * SK;
    __nv_bfloat16* Bl = Bh + (size_t)N * SK;

    const int t = threadIdx.x;
    const int lane = t & 31;
    const int wid = t >> 5;
    const int wm = wid & 3;         // warp row block (32 rows)
    const int wn = wid >> 2;        // warp col block (WN cols)
    const int row0 = blockIdx.x * BM;

    // ---- Fill A (fp32 -> hi/lo bf16), vectorized ----
    for (int i = t; i < BM * K / 4; i += 256) {
        int row = (i * 4) / K;
        int col = (i * 4) % K;
        float4 v = make_float4(0.f, 0.f, 0.f, 0.f);
        int gr = row0 + row;
        if (gr < nrows) {
            v = __ldg(reinterpret_cast<const float4*>(X + (size_t)gr * K) + (col >> 2));
            if (HAS_AGG) {
                float4 a = __ldg(reinterpret_cast<const float4*>(AGG + (size_t)gr * K) + (col >> 2));
                v.x += a.x; v.y += a.y; v.z += a.z; v.w += a.w;
            }
        }
        __nv_bfloat16 h0, h1, h2, h3, l0, l1, l2, l3;
        split2(v.x, h0, l0); split2(v.y, h1, l1);
        split2(v.z, h2, l2); split2(v.w, h3, l3);
        int o = row * SK + col;
        *reinterpret_cast<uint32_t*>(&Ah[o])     = pack_bf2(h0, h1);
        *reinterpret_cast<uint32_t*>(&Ah[o + 2]) = pack_bf2(h2, h3);
        *reinterpret_cast<uint32_t*>(&Al[o])     = pack_bf2(l0, l1);
        *reinterpret_cast<uint32_t*>(&Al[o + 2]) = pack_bf2(l2, l3);
    }

    // ---- Fill B = W^T (coalesced read over n) ----
    for (int i = t; i < N * K; i += 256) {
        int n = i % N;
        int k = i / N;
        float w = __ldg(&W[(size_t)k * N + n]);
        __nv_bfloat16 h, l;
        split2(w, h, l);
        Bh[n * SK + k] = h;
        Bl[n * SK + k] = l;
    }
    __syncthreads();

    // ---- Main compute ----
    float acc[2][NT][4] = {};
    for (int ks = 0; ks < KS; ks++) {
        const int k0 = ks * 16;
        const int tt = lane >> 3;
        const int tr = lane & 7;

        uint32_t a[2][2][4]; // [mtile][hi/lo][4]
#pragma unroll
        for (int mt = 0; mt < 2; mt++) {
            int r = wm * 32 + mt * 16 + (tt & 1) * 8 + tr;
            int c = k0 + (tt >> 1) * 8;
            LDMATRIX_X4(a[mt][0][0], a[mt][0][1], a[mt][0][2], a[mt][0][3],
                        smem_u32(&Ah[r * SK + c]));
            LDMATRIX_X4(a[mt][1][0], a[mt][1][1], a[mt][1][2], a[mt][1][3],
                        smem_u32(&Al[r * SK + c]));
        }

        uint32_t b[NT][2][2]; // [ntile][hi/lo][2]
#pragma unroll
        for (int p = 0; p < NT / 2; p++) {
            int n = wn * WN + p * 16 + (tt >> 1) * 8 + tr;
            int c = k0 + (tt & 1) * 8;
            uint32_t r0, r1, r2, r3;
            LDMATRIX_X4(r0, r1, r2, r3, smem_u32(&Bh[n * SK + c]));
            b[2*p][0][0] = r0; b[2*p][0][1] = r1;
            b[2*p+1][0][0] = r2; b[2*p+1][0][1] = r3;
            LDMATRIX_X4(r0, r1, r2, r3, smem_u32(&Bl[n * SK + c]));
            b[2*p][1][0] = r0; b[2*p][1][1] = r1;
            b[2*p+1][1][0] = r2; b[2*p+1][1][1] = r3;
        }

        // hi*hi, hi*lo, lo*hi — product-major so consecutive mmas are independent
#pragma unroll
        for (int mt = 0; mt < 2; mt++)
#pragma unroll
            for (int nt = 0; nt < NT; nt++)
                mma_bf16(acc[mt][nt], a[mt][0], b[nt][0]);
#pragma unroll
        for (int mt = 0; mt < 2; mt++)
#pragma unroll
            for (int nt = 0; nt < NT; nt++)
                mma_bf16(acc[mt][nt], a[mt][0], b[nt][1]);
#pragma unroll
        for (int mt = 0; mt < 2; mt++)
#pragma unroll
            for (int nt = 0; nt < NT; nt++)
                mma_bf16(acc[mt][nt], a[mt][1], b[nt][0]);
    }

    // ---- Epilogue ----
#pragma unroll
    for (int mt = 0; mt < 2; mt++) {
        int r_lo = row0 + wm * 32 + mt * 16 + (lane >> 2);
        int r_hi = r_lo + 8;
#pragma unroll
        for (int nt = 0; nt < NT; nt++) {
            int col = wn * WN + nt * 8 + (lane & 3) * 2;
            float bi0 = __ldg(&Bv[col]);
            float bi1 = __ldg(&Bv[col + 1]);
            if (r_lo < nrows) {
                float o0 = acc[mt][nt][0] + bi0;
                float o1 = acc[mt][nt][1] + bi1;
                if (RELU) { o0 = fmaxf(o0, 0.f); o1 = fmaxf(o1, 0.f); }
                if (RESID) {
                    float2 rr = __ldg(reinterpret_cast<const float2*>(RES + (size_t)r_lo * N + col));
                    o0 += rr.x; o1 += rr.y;
                }
                *reinterpret_cast<float2*>(OUT + (size_t)r_lo * N + col) = make_float2(o0, o1);
            }
            if (r_hi < nrows) {
                float o0 = acc[mt][nt][2] + bi0;
                float o1 = acc[mt][nt][3] + bi1;
                if (RELU) { o0 = fmaxf(o0, 0.f); o1 = fmaxf(o1, 0.f); }
                if (RESID) {
                    float2 rr = __ldg(reinterpret_cast<const float2*>(RES + (size_t)r_hi * N + col));
                    o0 += rr.x; o1 += rr.y;
                }
                *reinterpret_cast<float2*>(OUT + (size_t)r_hi * N + col) = make_float2(o0, o1);
            }
        }
    }
}

// ===================== Launch ====================
extern "C" void kernel_launch(void* const* d_in, const int* in_sizes, int n_in,
                              void* d_out, int out_size)
{
    const float* x  = (const float*)d_in[0];
    const int*   ei = (const int*)d_in[1];
    const float* W0 = (const float*)d_in[2];
    const float* b0 = (const float*)d_in[3];
    const float* W1 = (const float*)d_in[4];
    const float* b1 = (const float*)d_in[5];
    const float* W2 = (const float*)d_in[6];
    const float* b2 = (const float*)d_in[7];
    const float* Wp = (const float*)d_in[8];
    const float* bp = (const float*)d_in[9];
    float* out = (float*)d_out;

    const int n_nodes = in_sizes[0] / 64;
    const int n_edges = in_sizes[1] / 2;

    float *agg, *h0, *h1;
    cudaGetSymbolAddress((void**)&agg, g_agg);
    cudaGetSymbolAddress((void**)&h0,  g_h0);
    cudaGetSymbolAddress((void**)&h1,  g_h1);
    float* h2 = h0;

    const int agg_blocks   = (n_edges + 7) / 8;
    const int agg64_blocks = (n_edges + 15) / 16;
    const int gemm_blocks  = (n_nodes + 127) / 128;

    // smem bytes: (2*BM*SK + 2*N*SK) * 2
    const int smem_l0 = (2 * 128 * 72  + 2 * 128 * 72)  * 2;  // K=64,N=128: 73728
    const int smem_l  = (2 * 128 * 136 + 2 * 128 * 136) * 2;  // K=128,N=128: 139264
    const int smem_pr = (2 * 128 * 136 + 2 * 32  * 136) * 2;  // K=128,N=32: 87040
    cudaFuncSetAttribute(gemm_mma<64, 128, true, true, false>,
                         cudaFuncAttributeMaxDynamicSharedMemorySize, smem_l0);
    cudaFuncSetAttribute(gemm_mma<128, 128, true, true, true>,
                         cudaFuncAttributeMaxDynamicSharedMemorySize, smem_l);
    cudaFuncSetAttribute(gemm_mma<128, 32, false, false, false>,
                         cudaFuncAttributeMaxDynamicSharedMemorySize, smem_pr);

    // ---- Layer 0: h0 = relu((x + agg(x)) @ W0 + b0)
    cudaMemsetAsync(agg, 0, (size_t)n_nodes * 64 * sizeof(float));
    agg64_kernel<<<agg64_blocks, 256>>>(x, ei, agg, n_edges);
    gemm_mma<64, 128, true, true, false>
        <<<gemm_blocks, 256, smem_l0>>>(x, agg, W0, b0, nullptr, h0, n_nodes);

    // ---- Layer 1: h1 = relu((h0 + agg(h0)) @ W1 + b1) + h0
    cudaMemsetAsync(agg, 0, (size_t)n_nodes * 128 * sizeof(float));
    agg128_kernel<<<agg_blocks, 256>>>(h0, ei, agg, n_edges);
    gemm_mma<128, 128, true, true, true>
        <<<gemm_blocks, 256, smem_l>>>(h0, agg, W1, b1, h0, h1, n_nodes);

    // ---- Layer 2: h2 = relu((h1 + agg(h1)) @ W2 + b2) + h1
    cudaMemsetAsync(agg, 0, (size_t)n_nodes * 128 * sizeof(float));
    agg128_kernel<<<agg_blocks, 256>>>(h1, ei, agg, n_edges);
    gemm_mma<128, 128, true, true, true>
        <<<gemm_blocks, 256, smem_l>>>(h1, agg, W2, b2, h1, h2, n_nodes);

    // ---- Projection: out = h2 @ Wp + bp
    gemm_mma<128, 32, false, false, false>
        <<<gemm_blocks, 256, smem_pr>>>(h2, nullptr, Wp, bp, nullptr, out, n_nodes);
}

// round 6
// speedup vs baseline: 2.4732x; 1.3520x over previous
#include <cuda_runtime.h>
#include <cuda_bf16.h>
#include <cstdint>

// ---------------------------------------------------------------------------
// EigenGIN: 3x GINConv(sum-agg + Linear + ReLU, residual) + projection.
// CSR pull-mode aggregation (built once per launch), mma.sync bf16-pair GEMMs
// with pre-transposed/pre-split weights.
// ---------------------------------------------------------------------------

#define MAX_NODES 50000
#define MAX_EDGES 800000

__device__ float g_sum[MAX_NODES * 128];   // x_i + sum_j x_j (GEMM input A)
__device__ float g_h0 [MAX_NODES * 128];
__device__ float g_h1 [MAX_NODES * 128];

__device__ int g_row[MAX_NODES + 1];
__device__ int g_cur[MAX_NODES];           // counts, then cursor
__device__ int g_csr[MAX_EDGES];

// WT buffers (bf16 hi/lo, [N][K] layout): w0 8192 | w1 16384 | w2 16384 | wp 4096
#define WT0_OFF 0
#define WT1_OFF 8192
#define WT2_OFF 24576
#define WTP_OFF 40960
__device__ __nv_bfloat16 g_wthi[45056];
__device__ __nv_bfloat16 g_wtlo[45056];

// ===================== helpers ====================
__device__ __forceinline__ uint32_t smem_u32(const void* p) {
    uint32_t a;
    asm("{ .reg .u64 t; cvta.to.shared.u64 t, %1; cvt.u32.u64 %0, t; }"
        : "=r"(a) : "l"(p));
    return a;
}

#define LDMATRIX_X4(R0, R1, R2, R3, ADDR) \
    asm volatile("ldmatrix.sync.aligned.m8n8.x4.shared.b16 {%0,%1,%2,%3}, [%4];" \
                 : "=r"(R0), "=r"(R1), "=r"(R2), "=r"(R3) : "r"(ADDR))

__device__ __forceinline__ void mma_bf16(float* c, const uint32_t* a, const uint32_t* b) {
    asm volatile(
        "mma.sync.aligned.m16n8k16.row.col.f32.bf16.bf16.f32 "
        "{%0,%1,%2,%3}, {%4,%5,%6,%7}, {%8,%9}, {%0,%1,%2,%3};"
        : "+f"(c[0]), "+f"(c[1]), "+f"(c[2]), "+f"(c[3])
        : "r"(a[0]), "r"(a[1]), "r"(a[2]), "r"(a[3]), "r"(b[0]), "r"(b[1]));
}

__device__ __forceinline__ uint32_t pack_bf2(__nv_bfloat16 a, __nv_bfloat16 b) {
    return (uint32_t)__bfloat16_as_ushort(a) | ((uint32_t)__bfloat16_as_ushort(b) << 16);
}
__device__ __forceinline__ void split2(float f, __nv_bfloat16& h, __nv_bfloat16& l) {
    h = __float2bfloat16(f);
    l = __float2bfloat16(f - __bfloat162float(h));
}

// ===================== CSR build ====================
__global__ void count_kernel(const int* __restrict__ ei, int* __restrict__ counts,
                             int n_edges)
{
    int e = blockIdx.x * blockDim.x + threadIdx.x;
    if (e < n_edges) atomicAdd(&counts[__ldg(&ei[n_edges + e])], 1);
}

__global__ void scan_kernel(int* __restrict__ counts,   // in: counts, out: cursor
                            int* __restrict__ row_start,
                            int n)
{
    __shared__ int sdata[1024];
    __shared__ int carry;
    if (threadIdx.x == 0) carry = 0;
    __syncthreads();
    for (int base = 0; base < n; base += 1024) {
        int i = base + threadIdx.x;
        int v = (i < n) ? counts[i] : 0;
        sdata[threadIdx.x] = v;
        __syncthreads();
        for (int off = 1; off < 1024; off <<= 1) {
            int tv = (threadIdx.x >= off) ? sdata[threadIdx.x - off] : 0;
            __syncthreads();
            sdata[threadIdx.x] += tv;
            __syncthreads();
        }
        int excl = sdata[threadIdx.x] - v;
        int c = carry;
        if (i < n) { row_start[i] = c + excl; counts[i] = c + excl; }
        __syncthreads();
        if (threadIdx.x == 1023) carry = c + sdata[1023];
        __syncthreads();
    }
    if (threadIdx.x == 0) row_start[n] = carry;
}

__global__ void fill_kernel(const int* __restrict__ ei, int* __restrict__ cursor,
                            int* __restrict__ csr_src, int n_edges)
{
    int e = blockIdx.x * blockDim.x + threadIdx.x;
    if (e < n_edges) {
        int d = __ldg(&ei[n_edges + e]);
        int s = __ldg(&ei[e]);
        int pos = atomicAdd(&cursor[d], 1);
        csr_src[pos] = s;
    }
}

// ===================== Pull aggregation (includes self) ====================
// out[n] = feat[n] + sum_{s in nbrs(n)} feat[s]
__global__ void pull128_kernel(const float* __restrict__ feat,
                               const int* __restrict__ row_start,
                               const int* __restrict__ csr_src,
                               float* __restrict__ out, int n_nodes)
{
    int node = (blockIdx.x * blockDim.x + threadIdx.x) >> 5;
    int lane = threadIdx.x & 31;
    if (node >= n_nodes) return;
    int e0 = __ldg(&row_start[node]);
    int e1 = __ldg(&row_start[node + 1]);
    float4 acc = __ldg(reinterpret_cast<const float4*>(feat + (size_t)node * 128) + lane);
    int e = e0;
    for (; e + 1 < e1; e += 2) {
        int s0 = __ldg(&csr_src[e]);
        int s1 = __ldg(&csr_src[e + 1]);
        float4 v0 = __ldg(reinterpret_cast<const float4*>(feat + (size_t)s0 * 128) + lane);
        float4 v1 = __ldg(reinterpret_cast<const float4*>(feat + (size_t)s1 * 128) + lane);
        acc.x += v0.x + v1.x; acc.y += v0.y + v1.y;
        acc.z += v0.z + v1.z; acc.w += v0.w + v1.w;
    }
    if (e < e1) {
        int s = __ldg(&csr_src[e]);
        float4 v = __ldg(reinterpret_cast<const float4*>(feat + (size_t)s * 128) + lane);
        acc.x += v.x; acc.y += v.y; acc.z += v.z; acc.w += v.w;
    }
    *reinterpret_cast<float4*>(out + (size_t)node * 128 + lane * 4) = acc;
}

__global__ void pull64_kernel(const float* __restrict__ feat,
                              const int* __restrict__ row_start,
                              const int* __restrict__ csr_src,
                              float* __restrict__ out, int n_nodes)
{
    int gw   = (blockIdx.x * blockDim.x + threadIdx.x) >> 5;
    int lane = threadIdx.x & 31;
    int node = gw * 2 + (lane >> 4);
    int sub  = lane & 15;
    if (node >= n_nodes) return;
    int e0 = __ldg(&row_start[node]);
    int e1 = __ldg(&row_start[node + 1]);
    float4 acc = __ldg(reinterpret_cast<const float4*>(feat + (size_t)node * 64) + sub);
    int e = e0;
    for (; e + 1 < e1; e += 2) {
        int s0 = __ldg(&csr_src[e]);
        int s1 = __ldg(&csr_src[e + 1]);
        float4 v0 = __ldg(reinterpret_cast<const float4*>(feat + (size_t)s0 * 64) + sub);
        float4 v1 = __ldg(reinterpret_cast<const float4*>(feat + (size_t)s1 * 64) + sub);
        acc.x += v0.x + v1.x; acc.y += v0.y + v1.y;
        acc.z += v0.z + v1.z; acc.w += v0.w + v1.w;
    }
    if (e < e1) {
        int s = __ldg(&csr_src[e]);
        float4 v = __ldg(reinterpret_cast<const float4*>(feat + (size_t)s * 64) + sub);
        acc.x += v.x; acc.y += v.y; acc.z += v.z; acc.w += v.w;
    }
    *reinterpret_cast<float4*>(out + (size_t)node * 64 + sub * 4) = acc;
}

// ===================== Weight transpose+split (once per launch) ============
__global__ void wtrans_kernel(const float* __restrict__ W,
                              __nv_bfloat16* __restrict__ hi,
                              __nv_bfloat16* __restrict__ lo,
                              int K, int N)
{
    int i = blockIdx.x * blockDim.x + threadIdx.x;
    if (i >= K * N) return;
    int k = i / N, n = i % N;
    __nv_bfloat16 h, l;
    split2(__ldg(&W[i]), h, l);
    hi[n * K + k] = h;
    lo[n * K + k] = l;
}

// ===================== mma.sync GEMM ====================
// OUT[M,N] = [relu](X @ W + b) [+RES]; X already includes aggregation.
// WT_hi/WT_lo: [N][K] bf16. Warps 4(M) x 2(N).
template <int K, int N, bool RELU, bool RESID>
__global__ __launch_bounds__(256)
void gemm_mma(const float* __restrict__ X,
              const __nv_bfloat16* __restrict__ WT_hi,
              const __nv_bfloat16* __restrict__ WT_lo,
              const float* __restrict__ Bv,
              const float* __restrict__ RES,
              float* __restrict__ OUT,
              int nrows)
{
    constexpr int BM = 128;
    constexpr int SK = K + 8;
    constexpr int WN = N / 2;
    constexpr int NT = WN / 8;
    constexpr int KS = K / 16;

    extern __shared__ __nv_bfloat16 smem[];
    __nv_bfloat16* Ah = smem;
    __nv_bfloat16* Al = Ah + BM * SK;
    __nv_bfloat16* Bh = Al + BM * SK;
    __nv_bfloat16* Bl = Bh + (size_t)N * SK;

    const int t = threadIdx.x;
    const int lane = t & 31;
    const int wid = t >> 5;
    const int wm = wid & 3;
    const int wn = wid >> 2;
    const int row0 = blockIdx.x * BM;

    // ---- Fill A (fp32 -> hi/lo bf16) ----
    for (int i = t; i < BM * K / 4; i += 256) {
        int row = (i * 4) / K;
        int col = (i * 4) % K;
        float4 v = make_float4(0.f, 0.f, 0.f, 0.f);
        int gr = row0 + row;
        if (gr < nrows)
            v = __ldg(reinterpret_cast<const float4*>(X + (size_t)gr * K) + (col >> 2));
        __nv_bfloat16 h0, h1, h2, h3, l0, l1, l2, l3;
        split2(v.x, h0, l0); split2(v.y, h1, l1);
        split2(v.z, h2, l2); split2(v.w, h3, l3);
        int o = row * SK + col;
        *reinterpret_cast<uint32_t*>(&Ah[o])     = pack_bf2(h0, h1);
        *reinterpret_cast<uint32_t*>(&Ah[o + 2]) = pack_bf2(h2, h3);
        *reinterpret_cast<uint32_t*>(&Al[o])     = pack_bf2(l0, l1);
        *reinterpret_cast<uint32_t*>(&Al[o + 2]) = pack_bf2(l2, l3);
    }

    // ---- Fill B from pre-transposed bf16 (vectorized 16B copies) ----
    for (int i = t; i < N * K / 8; i += 256) {
        int n = (i * 8) / K;
        int k = (i * 8) % K;
        uint4 vh = __ldg(reinterpret_cast<const uint4*>(WT_hi) + i);
        uint4 vl = __ldg(reinterpret_cast<const uint4*>(WT_lo) + i);
        *reinterpret_cast<uint4*>(&Bh[n * SK + k]) = vh;
        *reinterpret_cast<uint4*>(&Bl[n * SK + k]) = vl;
    }
    __syncthreads();

    // ---- Main compute ----
    float acc[2][NT][4] = {};
    for (int ks = 0; ks < KS; ks++) {
        const int k0 = ks * 16;
        const int tt = lane >> 3;
        const int tr = lane & 7;

        uint32_t a[2][2][4];
#pragma unroll
        for (int mt = 0; mt < 2; mt++) {
            int r = wm * 32 + mt * 16 + (tt & 1) * 8 + tr;
            int c = k0 + (tt >> 1) * 8;
            LDMATRIX_X4(a[mt][0][0], a[mt][0][1], a[mt][0][2], a[mt][0][3],
                        smem_u32(&Ah[r * SK + c]));
            LDMATRIX_X4(a[mt][1][0], a[mt][1][1], a[mt][1][2], a[mt][1][3],
                        smem_u32(&Al[r * SK + c]));
        }

        uint32_t b[NT][2][2];
#pragma unroll
        for (int p = 0; p < NT / 2; p++) {
            int n = wn * WN + p * 16 + (tt >> 1) * 8 + tr;
            int c = k0 + (tt & 1) * 8;
            uint32_t r0, r1, r2, r3;
            LDMATRIX_X4(r0, r1, r2, r3, smem_u32(&Bh[n * SK + c]));
            b[2*p][0][0] = r0; b[2*p][0][1] = r1;
            b[2*p+1][0][0] = r2; b[2*p+1][0][1] = r3;
            LDMATRIX_X4(r0, r1, r2, r3, smem_u32(&Bl[n * SK + c]));
            b[2*p][1][0] = r0; b[2*p][1][1] = r1;
            b[2*p+1][1][0] = r2; b[2*p+1][1][1] = r3;
        }

#pragma unroll
        for (int mt = 0; mt < 2; mt++)
#pragma unroll
            for (int nt = 0; nt < NT; nt++)
                mma_bf16(acc[mt][nt], a[mt][0], b[nt][0]);
#pragma unroll
        for (int mt = 0; mt < 2; mt++)
#pragma unroll
            for (int nt = 0; nt < NT; nt++)
                mma_bf16(acc[mt][nt], a[mt][0], b[nt][1]);
#pragma unroll
        for (int mt = 0; mt < 2; mt++)
#pragma unroll
            for (int nt = 0; nt < NT; nt++)
                mma_bf16(acc[mt][nt], a[mt][1], b[nt][0]);
    }

    // ---- Epilogue ----
#pragma unroll
    for (int mt = 0; mt < 2; mt++) {
        int r_lo = row0 + wm * 32 + mt * 16 + (lane >> 2);
        int r_hi = r_lo + 8;
#pragma unroll
        for (int nt = 0; nt < NT; nt++) {
            int col = wn * WN + nt * 8 + (lane & 3) * 2;
            float bi0 = __ldg(&Bv[col]);
            float bi1 = __ldg(&Bv[col + 1]);
            if (r_lo < nrows) {
                float o0 = acc[mt][nt][0] + bi0;
                float o1 = acc[mt][nt][1] + bi1;
                if (RELU) { o0 = fmaxf(o0, 0.f); o1 = fmaxf(o1, 0.f); }
                if (RESID) {
                    float2 rr = __ldg(reinterpret_cast<const float2*>(RES + (size_t)r_lo * N + col));
                    o0 += rr.x; o1 += rr.y;
                }
                *reinterpret_cast<float2*>(OUT + (size_t)r_lo * N + col) = make_float2(o0, o1);
            }
            if (r_hi < nrows) {
                float o0 = acc[mt][nt][2] + bi0;
                float o1 = acc[mt][nt][3] + bi1;
                if (RELU) { o0 = fmaxf(o0, 0.f); o1 = fmaxf(o1, 0.f); }
                if (RESID) {
                    float2 rr = __ldg(reinterpret_cast<const float2*>(RES + (size_t)r_hi * N + col));
                    o0 += rr.x; o1 += rr.y;
                }
                *reinterpret_cast<float2*>(OUT + (size_t)r_hi * N + col) = make_float2(o0, o1);
            }
        }
    }
}

// ===================== Launch ====================
extern "C" void kernel_launch(void* const* d_in, const int* in_sizes, int n_in,
                              void* d_out, int out_size)
{
    const float* x  = (const float*)d_in[0];
    const int*   ei = (const int*)d_in[1];
    const float* W0 = (const float*)d_in[2];
    const float* b0 = (const float*)d_in[3];
    const float* W1 = (const float*)d_in[4];
    const float* b1 = (const float*)d_in[5];
    const float* W2 = (const float*)d_in[6];
    const float* b2 = (const float*)d_in[7];
    const float* Wp = (const float*)d_in[8];
    const float* bp = (const float*)d_in[9];
    float* out = (float*)d_out;

    const int n_nodes = in_sizes[0] / 64;
    const int n_edges = in_sizes[1] / 2;

    float *sum, *h0, *h1;
    int *row, *cur, *csr;
    __nv_bfloat16 *wthi, *wtlo;
    cudaGetSymbolAddress((void**)&sum,  g_sum);
    cudaGetSymbolAddress((void**)&h0,   g_h0);
    cudaGetSymbolAddress((void**)&h1,   g_h1);
    cudaGetSymbolAddress((void**)&row,  g_row);
    cudaGetSymbolAddress((void**)&cur,  g_cur);
    cudaGetSymbolAddress((void**)&csr,  g_csr);
    cudaGetSymbolAddress((void**)&wthi, g_wthi);
    cudaGetSymbolAddress((void**)&wtlo, g_wtlo);
    float* h2 = h0;

    const int eb = (n_edges + 255) / 256;
    const int pull128_blocks = (n_nodes + 7) / 8;     // warp per node
    const int pull64_blocks  = (n_nodes + 15) / 16;   // half-warp per node
    const int gemm_blocks    = (n_nodes + 127) / 128;

    const int smem_l0 = (2 * 128 * 72  + 2 * 128 * 72)  * 2;  // 73728
    const int smem_l  = (2 * 128 * 136 + 2 * 128 * 136) * 2;  // 139264
    const int smem_pr = (2 * 128 * 136 + 2 * 32  * 136) * 2;  // 87040
    cudaFuncSetAttribute(gemm_mma<64, 128, true, false>,
                         cudaFuncAttributeMaxDynamicSharedMemorySize, smem_l0);
    cudaFuncSetAttribute(gemm_mma<128, 128, true, true>,
                         cudaFuncAttributeMaxDynamicSharedMemorySize, smem_l);
    cudaFuncSetAttribute(gemm_mma<128, 32, false, false>,
                         cudaFuncAttributeMaxDynamicSharedMemorySize, smem_pr);

    // ---- One-time per launch: weight transforms + CSR build ----
    wtrans_kernel<<<(64 * 128 + 255) / 256, 256>>>(W0, wthi + WT0_OFF, wtlo + WT0_OFF, 64, 128);
    wtrans_kernel<<<(128 * 128 + 255) / 256, 256>>>(W1, wthi + WT1_OFF, wtlo + WT1_OFF, 128, 128);
    wtrans_kernel<<<(128 * 128 + 255) / 256, 256>>>(W2, wthi + WT2_OFF, wtlo + WT2_OFF, 128, 128);
    wtrans_kernel<<<(128 * 32 + 255) / 256, 256>>>(Wp, wthi + WTP_OFF, wtlo + WTP_OFF, 128, 32);

    cudaMemsetAsync(cur, 0, (size_t)n_nodes * sizeof(int));
    count_kernel<<<eb, 256>>>(ei, cur, n_edges);
    scan_kernel<<<1, 1024>>>(cur, row, n_nodes);
    fill_kernel<<<eb, 256>>>(ei, cur, csr, n_edges);

    // ---- Layer 0 ----
    pull64_kernel<<<pull64_blocks, 256>>>(x, row, csr, sum, n_nodes);
    gemm_mma<64, 128, true, false>
        <<<gemm_blocks, 256, smem_l0>>>(sum, wthi + WT0_OFF, wtlo + WT0_OFF, b0, nullptr, h0, n_nodes);

    // ---- Layer 1 ----
    pull128_kernel<<<pull128_blocks, 256>>>(h0, row, csr, sum, n_nodes);
    gemm_mma<128, 128, true, true>
        <<<gemm_blocks, 256, smem_l>>>(sum, wthi + WT1_OFF, wtlo + WT1_OFF, b1, h0, h1, n_nodes);

    // ---- Layer 2 ----
    pull128_kernel<<<pull128_blocks, 256>>>(h1, row, csr, sum, n_nodes);
    gemm_mma<128, 128, true, true>
        <<<gemm_blocks, 256, smem_l>>>(sum, wthi + WT2_OFF, wtlo + WT2_OFF, b2, h1, h2, n_nodes);

    // ---- Projection ----
    gemm_mma<128, 32, false, false>
        <<<gemm_blocks, 256, smem_pr>>>(h2, wthi + WTP_OFF, wtlo + WTP_OFF, bp, nullptr, out, n_nodes);
}